// round 8
// baseline (speedup 1.0000x reference)
#include <cuda_runtime.h>
#include <cstddef>

#define NNODES 50000
#define NEDGES 500000
#define HID    128
#define NGRAPH 256

// ---- scratch (device globals; no allocation allowed) ----
__device__ float g_h[(size_t)NNODES * HID];   // 25.6 MB
__device__ float g_t[(size_t)NNODES * HID];   // 25.6 MB
__device__ float g_deg[NNODES];               // weighted degree -> dinv
__device__ int   g_hist[NNODES];              // in-degree counts
__device__ int   g_rowptr[NNODES + 1];
__device__ int   g_cursor[NNODES];
__device__ int   g_bsum[64];
__device__ int   g_bpre[64];
__device__ int   g_csrc[NEDGES];
__device__ float g_cw[NEDGES];

// ---------------- CSR build ----------------
__global__ void k_init_nodes(float* deg, int* hist, int n) {
    int i = blockIdx.x * blockDim.x + threadIdx.x;
    if (i < n) { deg[i] = 1.0f; hist[i] = 0; }   // self-loop weight 1
}

__global__ void k_edge_hist(const int* __restrict__ dst, const float* __restrict__ ew,
                            float* deg, int* hist, int E) {
    int e = blockIdx.x * blockDim.x + threadIdx.x;
    if (e < E) {
        int d = dst[e];
        atomicAdd(&deg[d], ew[e]);
        atomicAdd(&hist[d], 1);
    }
}

__global__ void k_rsqrt(float* d, int n) {
    int i = blockIdx.x * blockDim.x + threadIdx.x;
    if (i < n) d[i] = rsqrtf(d[i]);
}

// per-block inclusive scan of hist (1024 elems/block) -> rowptr[1+i] (partial), bsum
__global__ void __launch_bounds__(1024) k_scan1(const int* __restrict__ hist,
                                                int* rowptr, int* bsum, int n) {
    __shared__ int s[1024];
    int t = threadIdx.x;
    int idx = blockIdx.x * 1024 + t;
    int v = (idx < n) ? hist[idx] : 0;
    s[t] = v;
    __syncthreads();
#pragma unroll
    for (int o = 1; o < 1024; o <<= 1) {
        int add = (t >= o) ? s[t - o] : 0;
        __syncthreads();
        s[t] += add;
        __syncthreads();
    }
    if (idx < n) rowptr[idx + 1] = s[t];
    if (t == 1023) bsum[blockIdx.x] = s[t];
}

__global__ void k_scan2(const int* bsum, int* bpre, int nb) {
    if (threadIdx.x == 0) {
        int run = 0;
        for (int b = 0; b < nb; b++) { bpre[b] = run; run += bsum[b]; }
    }
}

__global__ void __launch_bounds__(1024) k_scan3(int* rowptr, int* cursor,
                                                const int* bpre, int n) {
    int idx = blockIdx.x * 1024 + threadIdx.x;
    if (idx >= n) return;
    int val = rowptr[idx + 1] + bpre[blockIdx.x];
    rowptr[idx + 1] = val;
    if (idx + 1 < n) cursor[idx + 1] = val;
    if (idx == 0) { rowptr[0] = 0; cursor[0] = 0; }
}

__global__ void k_scatter(const int* __restrict__ src, const int* __restrict__ dst,
                          const float* __restrict__ ew, const float* __restrict__ dinv,
                          int* cursor, int* csrc, float* cw, int E) {
    int e = blockIdx.x * blockDim.x + threadIdx.x;
    if (e >= E) return;
    int s = src[e], d = dst[e];
    int pos = atomicAdd(&cursor[d], 1);
    csrc[pos] = s;
    cw[pos] = dinv[s] * ew[e] * dinv[d];
}

// ---------------- GEMM: O[n,128] = X[n,128] @ W^T (W row-major [j][k]) ----------------
// Packed-FFMA2 mainloop (fma.rn.f32x2). Both smem tiles stored k-major:
//   Xs[k*132 + r]  (r = row within tile),  Ws[k*132 + j]
__global__ void __launch_bounds__(256)
k_gemm(const float* __restrict__ X, const float* __restrict__ W,
       float* __restrict__ O, int nrows) {
    extern __shared__ float sm[];
    float* Xs = sm;                  // [128][132] k-major
    float* Ws = sm + 128 * 132;      // [128][132] k-major
    int tid = threadIdx.x;
    int tx = tid & 15, ty = tid >> 4;
    int row0 = blockIdx.x * 128;

#pragma unroll
    for (int i = 0; i < 16; i++) {
        int idx = i * 256 + tid;      // 0..4095 (float4 index)
        int r = idx >> 5, k4 = idx & 31;
        int grow = row0 + r;
        float4 v = make_float4(0.f, 0.f, 0.f, 0.f);
        if (grow < nrows) v = ((const float4*)(X + (size_t)grow * HID))[k4];
        Xs[(k4 * 4 + 0) * 132 + r] = v.x;
        Xs[(k4 * 4 + 1) * 132 + r] = v.y;
        Xs[(k4 * 4 + 2) * 132 + r] = v.z;
        Xs[(k4 * 4 + 3) * 132 + r] = v.w;
        float4 w = ((const float4*)W)[idx];    // W row j=r, cols k4*4..
        Ws[(k4 * 4 + 0) * 132 + r] = w.x;
        Ws[(k4 * 4 + 1) * 132 + r] = w.y;
        Ws[(k4 * 4 + 2) * 132 + r] = w.z;
        Ws[(k4 * 4 + 3) * 132 + r] = w.w;
    }
    __syncthreads();

    // acc pairs: acc2[i][jp] = (acc[i][2jp], acc[i][2jp+1]) packed f32x2
    unsigned long long acc2[8][4];
#pragma unroll
    for (int i = 0; i < 8; i++)
#pragma unroll
        for (int jp = 0; jp < 4; jp++) acc2[i][jp] = 0ull;

#pragma unroll 4
    for (int k = 0; k < 128; k++) {
        // a: 8 rows (ty*8..+7), contiguous in k-major Xs -> 2x LDS.128
        float4 af0 = *(const float4*)(Xs + k * 132 + ty * 8);
        float4 af1 = *(const float4*)(Xs + k * 132 + ty * 8 + 4);
        float a[8] = {af0.x, af0.y, af0.z, af0.w, af1.x, af1.y, af1.z, af1.w};
        // b: 8 cols (tx*8..+7) as 4 pre-packed f32x2 pairs -> 2x LDS.128
        ulonglong2 bq0 = *(const ulonglong2*)(Ws + k * 132 + tx * 8);
        ulonglong2 bq1 = *(const ulonglong2*)(Ws + k * 132 + tx * 8 + 4);
        unsigned long long b2[4] = {bq0.x, bq0.y, bq1.x, bq1.y};

        unsigned long long a2[8];
#pragma unroll
        for (int i = 0; i < 8; i++)
            asm("mov.b64 %0, {%1, %1};" : "=l"(a2[i]) : "f"(a[i]));

#pragma unroll
        for (int i = 0; i < 8; i++)
#pragma unroll
            for (int jp = 0; jp < 4; jp++)
                asm("fma.rn.f32x2 %0, %1, %2, %0;"
                    : "+l"(acc2[i][jp]) : "l"(a2[i]), "l"(b2[jp]));
    }

#pragma unroll
    for (int i = 0; i < 8; i++) {
        int grow = row0 + ty * 8 + i;
        if (grow < nrows) {
            float o[8];
#pragma unroll
            for (int jp = 0; jp < 4; jp++)
                asm("mov.b64 {%0, %1}, %2;"
                    : "=f"(o[jp * 2]), "=f"(o[jp * 2 + 1]) : "l"(acc2[i][jp]));
            float4 o0 = make_float4(o[0], o[1], o[2], o[3]);
            float4 o1 = make_float4(o[4], o[5], o[6], o[7]);
            *(float4*)(O + (size_t)grow * HID + tx * 8) = o0;
            *(float4*)(O + (size_t)grow * HID + tx * 8 + 4) = o1;
        }
    }
}

// ---------------- CSR gather aggregation, fused self-loop + bias + ReLU ----------------
// one warp per node: out[d] = relu( h[d]*dinv[d]^2 + sum_e c_e * h[src_e] + bias )
__global__ void __launch_bounds__(256)
k_agg_csr(const float* __restrict__ h, const int* __restrict__ rowptr,
          const int* __restrict__ csrc, const float* __restrict__ cw,
          const float* __restrict__ dinv, const float* __restrict__ bias,
          float* __restrict__ out, int n) {
    int gt = blockIdx.x * blockDim.x + threadIdx.x;
    int node = gt >> 5, lane = gt & 31;
    if (node >= n) return;
    const float4* h4 = (const float4*)h;

    float di = dinv[node];
    float c0 = di * di;
    float4 acc = h4[(size_t)node * 32 + lane];
    acc.x *= c0; acc.y *= c0; acc.z *= c0; acc.w *= c0;

    int beg = rowptr[node], end = rowptr[node + 1];
    int i = beg;
    for (; i + 1 < end; i += 2) {
        int   s0 = csrc[i],     s1 = csrc[i + 1];
        float w0 = cw[i],       w1 = cw[i + 1];
        float4 v0 = h4[(size_t)s0 * 32 + lane];
        float4 v1 = h4[(size_t)s1 * 32 + lane];
        acc.x += w0 * v0.x + w1 * v1.x;
        acc.y += w0 * v0.y + w1 * v1.y;
        acc.z += w0 * v0.z + w1 * v1.z;
        acc.w += w0 * v0.w + w1 * v1.w;
    }
    if (i < end) {
        int s = csrc[i]; float w = cw[i];
        float4 v = h4[(size_t)s * 32 + lane];
        acc.x += w * v.x; acc.y += w * v.y; acc.z += w * v.z; acc.w += w * v.w;
    }

    float4 b = ((const float4*)bias)[lane];
    acc.x = fmaxf(acc.x + b.x, 0.f);
    acc.y = fmaxf(acc.y + b.y, 0.f);
    acc.z = fmaxf(acc.z + b.z, 0.f);
    acc.w = fmaxf(acc.w + b.w, 0.f);
    ((float4*)out)[(size_t)node * 32 + lane] = acc;
}

// ---------------- fused mean-pool + MLP head (batch is sorted) ----------------
__global__ void __launch_bounds__(128)
k_poolmlp(const float* __restrict__ a, const int* __restrict__ batch, int n,
          const float* __restrict__ fW1, const float* __restrict__ fb1,
          const float* __restrict__ fW2, const float* __restrict__ fb2,
          float* __restrict__ out) {
    __shared__ int seg[2];
    __shared__ float p[128];
    __shared__ float z[128];
    int g = blockIdx.x, t = threadIdx.x;

    if (t < 2) {
        int key = g + t, lo = 0, hi = n;
        while (lo < hi) { int mid = (lo + hi) >> 1; if (batch[mid] < key) lo = mid + 1; else hi = mid; }
        seg[t] = lo;
    }
    __syncthreads();
    int start = seg[0], end = seg[1];

    float acc = 0.f;
    for (int i = start; i < end; i++) acc += a[(size_t)i * HID + t];
    float cnt = fmaxf((float)(end - start), 1.0f);
    p[t] = acc / cnt;
    __syncthreads();

    float s1 = fb1[t];
    const float* wr = fW1 + t * HID;
#pragma unroll 4
    for (int k = 0; k < HID; k++) s1 += p[k] * wr[k];
    z[t] = fmaxf(s1, 0.f) * fW2[t];
    __syncthreads();
    if (t < 32) {
        float s = z[t] + z[t + 32] + z[t + 64] + z[t + 96];
#pragma unroll
        for (int o = 16; o; o >>= 1) s += __shfl_down_sync(0xffffffffu, s, o);
        if (t == 0) out[g] = s + fb2[0];
    }
}

// ---------------- launch ----------------
extern "C" void kernel_launch(void* const* d_in, const int* in_sizes, int n_in,
                              void* d_out, int out_size) {
    const float* x     = (const float*)d_in[0];
    const int*   eidx  = (const int*)d_in[1];
    const float* eattr = (const float*)d_in[2];
    const int*   batch = (const int*)d_in[3];
    const float* W1    = (const float*)d_in[4];
    const float* b1    = (const float*)d_in[5];
    const float* W2    = (const float*)d_in[6];
    const float* b2    = (const float*)d_in[7];
    const float* fW1   = (const float*)d_in[8];
    const float* fb1   = (const float*)d_in[9];
    const float* fW2   = (const float*)d_in[10];
    const float* fb2   = (const float*)d_in[11];
    float* out = (float*)d_out;

    int N = in_sizes[0] / HID;
    int E = in_sizes[1] / 2;
    const int* src = eidx;
    const int* dst = eidx + E;

    float *p_h, *p_t, *p_deg, *p_cw;
    int *p_hist, *p_rowptr, *p_cursor, *p_bsum, *p_bpre, *p_csrc;
    cudaGetSymbolAddress((void**)&p_h, g_h);
    cudaGetSymbolAddress((void**)&p_t, g_t);
    cudaGetSymbolAddress((void**)&p_deg, g_deg);
    cudaGetSymbolAddress((void**)&p_hist, g_hist);
    cudaGetSymbolAddress((void**)&p_rowptr, g_rowptr);
    cudaGetSymbolAddress((void**)&p_cursor, g_cursor);
    cudaGetSymbolAddress((void**)&p_bsum, g_bsum);
    cudaGetSymbolAddress((void**)&p_bpre, g_bpre);
    cudaGetSymbolAddress((void**)&p_csrc, g_csrc);
    cudaGetSymbolAddress((void**)&p_cw, g_cw);

    const int T = 256;
    int gemm_blocks = (N + 127) / 128;
    int agg_blocks = (int)(((long long)N * 32 + T - 1) / T);
    int scan_blocks = (N + 1023) / 1024;
    size_t gemm_smem = (size_t)2 * 128 * 132 * sizeof(float);
    cudaFuncSetAttribute(k_gemm, cudaFuncAttributeMaxDynamicSharedMemorySize,
                         (int)gemm_smem);

    // ---- CSR build + normalization coefficients ----
    k_init_nodes<<<(N + T - 1) / T, T>>>(p_deg, p_hist, N);
    k_edge_hist<<<(E + T - 1) / T, T>>>(dst, eattr, p_deg, p_hist, E);
    k_rsqrt<<<(N + T - 1) / T, T>>>(p_deg, N);           // g_deg now holds dinv
    k_scan1<<<scan_blocks, 1024>>>(p_hist, p_rowptr, p_bsum, N);
    k_scan2<<<1, 32>>>(p_bsum, p_bpre, scan_blocks);
    k_scan3<<<scan_blocks, 1024>>>(p_rowptr, p_cursor, p_bpre, N);
    k_scatter<<<(E + T - 1) / T, T>>>(src, dst, eattr, p_deg, p_cursor, p_csrc, p_cw, E);

    // ---- layer 1 ----
    k_gemm<<<gemm_blocks, T, gemm_smem>>>(x, W1, p_h, N);
    k_agg_csr<<<agg_blocks, T>>>(p_h, p_rowptr, p_csrc, p_cw, p_deg, b1, p_t, N);

    // ---- layer 2 ----
    k_gemm<<<gemm_blocks, T, gemm_smem>>>(p_t, W2, p_h, N);
    k_agg_csr<<<agg_blocks, T>>>(p_h, p_rowptr, p_csrc, p_cw, p_deg, b2, p_t, N);

    // ---- pool + MLP ----
    k_poolmlp<<<NGRAPH, 128>>>(p_t, batch, N, fW1, fb1, fW2, fb2, out);
}

// round 11
// speedup vs baseline: 1.2637x; 1.2637x over previous
#include <cuda_runtime.h>
#include <cstddef>
#include <cstdint>

#define NNODES 50000
#define NEDGES 500000
#define HID    128
#define NGRAPH 256

// ---- scratch (device globals; no allocation allowed) ----
__device__ float g_h[(size_t)NNODES * HID];   // 25.6 MB
__device__ float g_t[(size_t)NNODES * HID];   // 25.6 MB
__device__ float g_deg[NNODES];               // weighted degree -> dinv
__device__ int   g_hist[NNODES];              // in-degree counts
__device__ int   g_rowptr[NNODES + 1];
__device__ int   g_cursor[NNODES];
__device__ int   g_bsum[64];
__device__ int   g_bpre[64];
__device__ int   g_csrc[NEDGES];
__device__ float g_cw[NEDGES];

// ---------------- CSR build ----------------
__global__ void k_init_nodes(float* deg, int* hist, int n) {
    int i = blockIdx.x * blockDim.x + threadIdx.x;
    if (i < n) { deg[i] = 1.0f; hist[i] = 0; }   // self-loop weight 1
}

__global__ void k_edge_hist(const int* __restrict__ dst, const float* __restrict__ ew,
                            float* deg, int* hist, int E) {
    int e = blockIdx.x * blockDim.x + threadIdx.x;
    if (e < E) {
        int d = dst[e];
        atomicAdd(&deg[d], ew[e]);
        atomicAdd(&hist[d], 1);
    }
}

__global__ void k_rsqrt(float* d, int n) {
    int i = blockIdx.x * blockDim.x + threadIdx.x;
    if (i < n) d[i] = rsqrtf(d[i]);
}

__global__ void __launch_bounds__(1024) k_scan1(const int* __restrict__ hist,
                                                int* rowptr, int* bsum, int n) {
    __shared__ int s[1024];
    int t = threadIdx.x;
    int idx = blockIdx.x * 1024 + t;
    int v = (idx < n) ? hist[idx] : 0;
    s[t] = v;
    __syncthreads();
#pragma unroll
    for (int o = 1; o < 1024; o <<= 1) {
        int add = (t >= o) ? s[t - o] : 0;
        __syncthreads();
        s[t] += add;
        __syncthreads();
    }
    if (idx < n) rowptr[idx + 1] = s[t];
    if (t == 1023) bsum[blockIdx.x] = s[t];
}

__global__ void k_scan2(const int* bsum, int* bpre, int nb) {
    if (threadIdx.x == 0) {
        int run = 0;
        for (int b = 0; b < nb; b++) { bpre[b] = run; run += bsum[b]; }
    }
}

__global__ void __launch_bounds__(1024) k_scan3(int* rowptr, int* cursor,
                                                const int* bpre, int n) {
    int idx = blockIdx.x * 1024 + threadIdx.x;
    if (idx >= n) return;
    int val = rowptr[idx + 1] + bpre[blockIdx.x];
    rowptr[idx + 1] = val;
    if (idx + 1 < n) cursor[idx + 1] = val;
    if (idx == 0) { rowptr[0] = 0; cursor[0] = 0; }
}

__global__ void k_scatter(const int* __restrict__ src, const int* __restrict__ dst,
                          const float* __restrict__ ew, const float* __restrict__ dinv,
                          int* cursor, int* csrc, float* cw, int E) {
    int e = blockIdx.x * blockDim.x + threadIdx.x;
    if (e >= E) return;
    int s = src[e], d = dst[e];
    int pos = atomicAdd(&cursor[d], 1);
    csrc[pos] = s;
    cw[pos] = dinv[s] * ew[e] * dinv[d];
}

// ================= tf32 mma.sync GEMM (sm_80+ PTX, no arch-accel features) =================
__device__ __forceinline__ uint32_t f2tf32(float x) {
    uint32_t r;
    asm("cvt.rna.tf32.f32 %0, %1;" : "=r"(r) : "f"(x));
    return r;
}

__device__ __forceinline__ void mma_tf32(float* d, const uint32_t* a, const uint32_t* b) {
    asm volatile(
        "mma.sync.aligned.m16n8k8.row.col.f32.tf32.tf32.f32 "
        "{%0,%1,%2,%3}, {%4,%5,%6,%7}, {%8,%9}, {%0,%1,%2,%3};"
        : "+f"(d[0]), "+f"(d[1]), "+f"(d[2]), "+f"(d[3])
        : "r"(a[0]), "r"(a[1]), "r"(a[2]), "r"(a[3]), "r"(b[0]), "r"(b[1]));
}

// smem layout (u32 elements), 132-padded rows
#define WHI 0
#define WLO (128 * 132)
#define XHI (2 * 128 * 132)
#define XLO (2 * 128 * 132 + 64 * 132)
#define GEMM_SMEM_BYTES ((2 * 128 * 132 + 2 * 64 * 132) * 4)

// O[n,128] = X[n,128] @ W^T.  Persistent; W split hi/lo cached in smem per block.
// 256 threads = 8 warps; tile = 64 rows; warp w owns N cols [16w, 16w+16).
// 3-term tf32: D = ahi*bhi + alo*bhi + ahi*blo  (near-fp32 accuracy)
__global__ void __launch_bounds__(256)
k_gemm_mma(const float* __restrict__ X, const float* __restrict__ W,
           float* __restrict__ O, int nrows, int ntiles) {
    extern __shared__ uint32_t sm[];
    int tid = threadIdx.x;
    int w = tid >> 5, lane = tid & 31;
    int rq = lane >> 2;      // quad/group id 0..7
    int rc = lane & 3;       // thread-in-group 0..3

    // ---- load W once: Whi/Wlo[k*132 + j] = tf32 split of W[j][k] ----
#pragma unroll
    for (int i = 0; i < 64; i++) {
        int idx = i * 256 + tid;          // 0..16383
        int j = idx >> 7, k = idx & 127;
        float v = W[idx];
        uint32_t hi = f2tf32(v);
        float lo = v - __uint_as_float(hi);
        sm[WHI + k * 132 + j] = hi;
        sm[WLO + k * 132 + j] = f2tf32(lo);
    }
    __syncthreads();

    for (int tile = blockIdx.x; tile < ntiles; tile += gridDim.x) {
        int row0 = tile * 64;

        // ---- load X tile (64 rows), split hi/lo ----
#pragma unroll
        for (int i = 0; i < 32; i++) {
            int idx = i * 256 + tid;      // 0..8191
            int r = idx >> 7, c = idx & 127;
            int grow = row0 + r;
            float v = (grow < nrows) ? X[(size_t)grow * HID + c] : 0.f;
            uint32_t hi = f2tf32(v);
            float lo = v - __uint_as_float(hi);
            sm[XHI + r * 132 + c] = hi;
            sm[XLO + r * 132 + c] = f2tf32(lo);
        }
        __syncthreads();

        float d[4][2][4];
#pragma unroll
        for (int rg = 0; rg < 4; rg++)
#pragma unroll
            for (int nt = 0; nt < 2; nt++)
#pragma unroll
                for (int q = 0; q < 4; q++) d[rg][nt][q] = 0.f;

#pragma unroll 2
        for (int k0 = 0; k0 < 16; k0++) {
            int kb = k0 * 8;
            uint32_t ahi[4][4], alo[4][4];
#pragma unroll
            for (int rg = 0; rg < 4; rg++) {
                int base = (rg * 16 + rq) * 132 + kb + rc;
                ahi[rg][0] = sm[XHI + base];
                ahi[rg][1] = sm[XHI + base + 8 * 132];
                ahi[rg][2] = sm[XHI + base + 4];
                ahi[rg][3] = sm[XHI + base + 8 * 132 + 4];
                alo[rg][0] = sm[XLO + base];
                alo[rg][1] = sm[XLO + base + 8 * 132];
                alo[rg][2] = sm[XLO + base + 4];
                alo[rg][3] = sm[XLO + base + 8 * 132 + 4];
            }
#pragma unroll
            for (int nt = 0; nt < 2; nt++) {
                int ncol = w * 16 + nt * 8 + rq;
                int bb = (kb + rc) * 132 + ncol;
                uint32_t bhi[2], blo[2];
                bhi[0] = sm[WHI + bb];
                bhi[1] = sm[WHI + bb + 4 * 132];
                blo[0] = sm[WLO + bb];
                blo[1] = sm[WLO + bb + 4 * 132];
#pragma unroll
                for (int rg = 0; rg < 4; rg++) {
                    mma_tf32(d[rg][nt], ahi[rg], bhi);
                    mma_tf32(d[rg][nt], alo[rg], bhi);
                    mma_tf32(d[rg][nt], ahi[rg], blo);
                }
            }
        }

        // ---- epilogue: direct STG.64 ----
#pragma unroll
        for (int rg = 0; rg < 4; rg++)
#pragma unroll
            for (int nt = 0; nt < 2; nt++) {
                int row = row0 + rg * 16 + rq;
                int col = w * 16 + nt * 8 + 2 * rc;
                if (row < nrows)
                    *(float2*)(O + (size_t)row * HID + col) =
                        make_float2(d[rg][nt][0], d[rg][nt][1]);
                if (row + 8 < nrows)
                    *(float2*)(O + (size_t)(row + 8) * HID + col) =
                        make_float2(d[rg][nt][2], d[rg][nt][3]);
            }
        __syncthreads();
    }
}

// ---------------- CSR gather aggregation, fused self-loop + bias + ReLU ----------------
__global__ void __launch_bounds__(256)
k_agg_csr(const float* __restrict__ h, const int* __restrict__ rowptr,
          const int* __restrict__ csrc, const float* __restrict__ cw,
          const float* __restrict__ dinv, const float* __restrict__ bias,
          float* __restrict__ out, int n) {
    int gt = blockIdx.x * blockDim.x + threadIdx.x;
    int node = gt >> 5, lane = gt & 31;
    if (node >= n) return;
    const float4* h4 = (const float4*)h;

    float di = dinv[node];
    float c0 = di * di;
    float4 acc = h4[(size_t)node * 32 + lane];
    acc.x *= c0; acc.y *= c0; acc.z *= c0; acc.w *= c0;

    int beg = rowptr[node], end = rowptr[node + 1];
    int i = beg;
    for (; i + 1 < end; i += 2) {
        int   s0 = csrc[i],     s1 = csrc[i + 1];
        float w0 = cw[i],       w1 = cw[i + 1];
        float4 v0 = h4[(size_t)s0 * 32 + lane];
        float4 v1 = h4[(size_t)s1 * 32 + lane];
        acc.x += w0 * v0.x + w1 * v1.x;
        acc.y += w0 * v0.y + w1 * v1.y;
        acc.z += w0 * v0.z + w1 * v1.z;
        acc.w += w0 * v0.w + w1 * v1.w;
    }
    if (i < end) {
        int s = csrc[i]; float w = cw[i];
        float4 v = h4[(size_t)s * 32 + lane];
        acc.x += w * v.x; acc.y += w * v.y; acc.z += w * v.z; acc.w += w * v.w;
    }

    float4 b = ((const float4*)bias)[lane];
    acc.x = fmaxf(acc.x + b.x, 0.f);
    acc.y = fmaxf(acc.y + b.y, 0.f);
    acc.z = fmaxf(acc.z + b.z, 0.f);
    acc.w = fmaxf(acc.w + b.w, 0.f);
    ((float4*)out)[(size_t)node * 32 + lane] = acc;
}

// ---------------- fused mean-pool + MLP head (batch is sorted) ----------------
__global__ void __launch_bounds__(128)
k_poolmlp(const float* __restrict__ a, const int* __restrict__ batch, int n,
          const float* __restrict__ fW1, const float* __restrict__ fb1,
          const float* __restrict__ fW2, const float* __restrict__ fb2,
          float* __restrict__ out) {
    __shared__ int seg[2];
    __shared__ float p[128];
    __shared__ float z[128];
    int g = blockIdx.x, t = threadIdx.x;

    if (t < 2) {
        int key = g + t, lo = 0, hi = n;
        while (lo < hi) { int mid = (lo + hi) >> 1; if (batch[mid] < key) lo = mid + 1; else hi = mid; }
        seg[t] = lo;
    }
    __syncthreads();
    int start = seg[0], end = seg[1];

    float acc = 0.f;
    for (int i = start; i < end; i++) acc += a[(size_t)i * HID + t];
    float cnt = fmaxf((float)(end - start), 1.0f);
    p[t] = acc / cnt;
    __syncthreads();

    float s1 = fb1[t];
    const float* wr = fW1 + t * HID;
#pragma unroll 4
    for (int k = 0; k < HID; k++) s1 += p[k] * wr[k];
    z[t] = fmaxf(s1, 0.f) * fW2[t];
    __syncthreads();
    if (t < 32) {
        float s = z[t] + z[t + 32] + z[t + 64] + z[t + 96];
#pragma unroll
        for (int o = 16; o; o >>= 1) s += __shfl_down_sync(0xffffffffu, s, o);
        if (t == 0) out[g] = s + fb2[0];
    }
}

// ---------------- launch ----------------
extern "C" void kernel_launch(void* const* d_in, const int* in_sizes, int n_in,
                              void* d_out, int out_size) {
    const float* x     = (const float*)d_in[0];
    const int*   eidx  = (const int*)d_in[1];
    const float* eattr = (const float*)d_in[2];
    const int*   batch = (const int*)d_in[3];
    const float* W1    = (const float*)d_in[4];
    const float* b1    = (const float*)d_in[5];
    const float* W2    = (const float*)d_in[6];
    const float* b2    = (const float*)d_in[7];
    const float* fW1   = (const float*)d_in[8];
    const float* fb1   = (const float*)d_in[9];
    const float* fW2   = (const float*)d_in[10];
    const float* fb2   = (const float*)d_in[11];
    float* out = (float*)d_out;

    int N = in_sizes[0] / HID;
    int E = in_sizes[1] / 2;
    const int* src = eidx;
    const int* dst = eidx + E;

    float *p_h, *p_t, *p_deg, *p_cw;
    int *p_hist, *p_rowptr, *p_cursor, *p_bsum, *p_bpre, *p_csrc;
    cudaGetSymbolAddress((void**)&p_h, g_h);
    cudaGetSymbolAddress((void**)&p_t, g_t);
    cudaGetSymbolAddress((void**)&p_deg, g_deg);
    cudaGetSymbolAddress((void**)&p_hist, g_hist);
    cudaGetSymbolAddress((void**)&p_rowptr, g_rowptr);
    cudaGetSymbolAddress((void**)&p_cursor, g_cursor);
    cudaGetSymbolAddress((void**)&p_bsum, g_bsum);
    cudaGetSymbolAddress((void**)&p_bpre, g_bpre);
    cudaGetSymbolAddress((void**)&p_csrc, g_csrc);
    cudaGetSymbolAddress((void**)&p_cw, g_cw);

    const int T = 256;
    int ntiles = (N + 63) / 64;
    int agg_blocks = (int)(((long long)N * 32 + T - 1) / T);
    int scan_blocks = (N + 1023) / 1024;
    cudaFuncSetAttribute(k_gemm_mma, cudaFuncAttributeMaxDynamicSharedMemorySize,
                         GEMM_SMEM_BYTES);

    // ---- CSR build + normalization coefficients ----
    k_init_nodes<<<(N + T - 1) / T, T>>>(p_deg, p_hist, N);
    k_edge_hist<<<(E + T - 1) / T, T>>>(dst, eattr, p_deg, p_hist, E);
    k_rsqrt<<<(N + T - 1) / T, T>>>(p_deg, N);           // g_deg now holds dinv
    k_scan1<<<scan_blocks, 1024>>>(p_hist, p_rowptr, p_bsum, N);
    k_scan2<<<1, 32>>>(p_bsum, p_bpre, scan_blocks);
    k_scan3<<<scan_blocks, 1024>>>(p_rowptr, p_cursor, p_bpre, N);
    k_scatter<<<(E + T - 1) / T, T>>>(src, dst, eattr, p_deg, p_cursor, p_csrc, p_cw, E);

    // ---- layer 1 ----
    k_gemm_mma<<<152, T, GEMM_SMEM_BYTES>>>(x, W1, p_h, N, ntiles);
    k_agg_csr<<<agg_blocks, T>>>(p_h, p_rowptr, p_csrc, p_cw, p_deg, b1, p_t, N);

    // ---- layer 2 ----
    k_gemm_mma<<<152, T, GEMM_SMEM_BYTES>>>(p_t, W2, p_h, N, ntiles);
    k_agg_csr<<<agg_blocks, T>>>(p_h, p_rowptr, p_csrc, p_cw, p_deg, b2, p_t, N);

    // ---- pool + MLP ----
    k_poolmlp<<<NGRAPH, 128>>>(p_t, batch, N, fW1, fb1, fW2, fb2, out);
}